// round 3
// baseline (speedup 1.0000x reference)
#include <cuda_runtime.h>
#include <cstdint>

// Problem constants
#define G      8
#define VCODES 512
#define HDIM   128
#define NTOK   16384          // B*T = 8*2048
#define TILE_N 64
#define TILE_V 128
#define XS_STRIDE 68          // 64 + 4 pad (keeps 16B row alignment)
#define ES_STRIDE 132         // 128 + 4 pad
#define SMEM_FLOATS (HDIM*XS_STRIDE + HDIM*ES_STRIDE)   // 25600 floats = 100 KB

// Scratch (device globals: no allocation allowed)
__device__ int   g_codes[G * NTOK];
__device__ float g_enorm[G * VCODES];

// ---------------------------------------------------------------------------
// Kernel 0: ||e||^2 per (g, code). 4096 rows of 128 floats.
// ---------------------------------------------------------------------------
__global__ void pq_enorm_kernel(const float* __restrict__ embed) {
    const int row  = blockIdx.x * 8 + (threadIdx.x >> 5);
    const int lane = threadIdx.x & 31;
    const float* e = embed + (size_t)row * HDIM;
    const float v0 = e[lane], v1 = e[lane + 32], v2 = e[lane + 64], v3 = e[lane + 96];
    float s = v0 * v0 + v1 * v1 + v2 * v2 + v3 * v3;
    #pragma unroll
    for (int off = 16; off; off >>= 1) s += __shfl_xor_sync(0xffffffffu, s, off);
    if (lane == 0) g_enorm[row] = s;
}

// ---------------------------------------------------------------------------
// Kernel 1: per (g, token) argmin over 512 codes of ||e||^2 - 2*x.e
// CTA = (64 tokens, 1 group). 256 threads = 8 warps.
// warp w owns tokens [w*8, w*8+8); lane owns 4 codes per 128-code chunk.
// Inner product via packed fp32 FFMA2 (fma.rn.f32x2).
// ---------------------------------------------------------------------------
#define FMA2(ACC, XP, ED) \
    asm("fma.rn.f32x2 %0, %1, %2, %0;" : "+l"(ACC) : "l"(XP), "l"(ED))

__global__ __launch_bounds__(256, 2) void pq_argmin_kernel(
    const float* __restrict__ x, const float* __restrict__ embed)
{
    extern __shared__ float smem[];
    float* xs = smem;                        // [HDIM][XS_STRIDE]  x transposed
    float* es = smem + HDIM * XS_STRIDE;     // [HDIM][ES_STRIDE]  embed chunk transposed

    const int g    = blockIdx.y;
    const int n0   = blockIdx.x * TILE_N;
    const int tid  = threadIdx.x;
    const int lane = tid & 31;
    const int w    = tid >> 5;

    // ---- load x tile transposed: xs[k][t]  (warp-broadcast-friendly reads) ----
    for (int t = w; t < TILE_N; t += 8) {
        const float4 v = *reinterpret_cast<const float4*>(
            x + (size_t)(n0 + t) * (G * HDIM) + (g * HDIM) + (lane << 2));
        const int k4 = lane << 2;
        xs[(k4 + 0) * XS_STRIDE + t] = v.x;
        xs[(k4 + 1) * XS_STRIDE + t] = v.y;
        xs[(k4 + 2) * XS_STRIDE + t] = v.z;
        xs[(k4 + 3) * XS_STRIDE + t] = v.w;
    }

    float best[8];
    int   bidx[8];
    #pragma unroll
    for (int t = 0; t < 8; t++) { best[t] = 3.4e38f; bidx[t] = 0; }

    const unsigned xs_base = (unsigned)__cvta_generic_to_shared(xs) + (w << 5);
    const unsigned es_base = (unsigned)__cvta_generic_to_shared(es) + (lane << 4);

    for (int v0 = 0; v0 < VCODES; v0 += TILE_V) {
        __syncthreads();   // previous chunk fully consumed

        // ---- fill es[k][c] transposed; STS conflict-free (consecutive c per lane) ----
        #pragma unroll
        for (int cg = 0; cg < 4; cg++) {
            const int c = (cg << 5) + lane;
            const float4* src = reinterpret_cast<const float4*>(
                embed + ((size_t)(g * VCODES) + v0 + c) * HDIM);
            #pragma unroll
            for (int s = 0; s < 4; s++) {
                const int k4 = (w << 4) + (s << 2);
                const float4 v = src[k4 >> 2];
                es[(k4 + 0) * ES_STRIDE + c] = v.x;
                es[(k4 + 1) * ES_STRIDE + c] = v.y;
                es[(k4 + 2) * ES_STRIDE + c] = v.z;
                es[(k4 + 3) * ES_STRIDE + c] = v.w;
            }
        }

        float en[4];
        {
            const float* ep = g_enorm + g * VCODES + v0 + (lane << 2);
            en[0] = ep[0]; en[1] = ep[1]; en[2] = ep[2]; en[3] = ep[3];
        }
        __syncthreads();

        // ---- 64x128x128 chunk GEMM fragment: 8 tokens x 4 codes per thread ----
        uint64_t acc[4][4];
        #pragma unroll
        for (int a = 0; a < 4; a++)
            #pragma unroll
            for (int b = 0; b < 4; b++) acc[a][b] = 0ull;

        unsigned xa = xs_base, ea = es_base;
        #pragma unroll 4
        for (int k = 0; k < HDIM; k++) {
            uint64_t x01, x23, x45, x67;
            // token pairs come pre-packed from adjacent SMEM floats
            asm volatile("ld.shared.v2.b64 {%0,%1}, [%2];"
                         : "=l"(x01), "=l"(x23) : "r"(xa));
            asm volatile("ld.shared.v2.b64 {%0,%1}, [%2];"
                         : "=l"(x45), "=l"(x67) : "r"(xa + 16));
            unsigned e0, e1, e2, e3;
            asm volatile("ld.shared.v4.b32 {%0,%1,%2,%3}, [%4];"
                         : "=r"(e0), "=r"(e1), "=r"(e2), "=r"(e3) : "r"(ea));
            uint64_t d0, d1, d2, d3;  // duplicate each code value into both halves
            asm("mov.b64 %0, {%1,%1};" : "=l"(d0) : "r"(e0));
            asm("mov.b64 %0, {%1,%1};" : "=l"(d1) : "r"(e1));
            asm("mov.b64 %0, {%1,%1};" : "=l"(d2) : "r"(e2));
            asm("mov.b64 %0, {%1,%1};" : "=l"(d3) : "r"(e3));

            FMA2(acc[0][0], x01, d0); FMA2(acc[0][1], x01, d1);
            FMA2(acc[0][2], x01, d2); FMA2(acc[0][3], x01, d3);
            FMA2(acc[1][0], x23, d0); FMA2(acc[1][1], x23, d1);
            FMA2(acc[1][2], x23, d2); FMA2(acc[1][3], x23, d3);
            FMA2(acc[2][0], x45, d0); FMA2(acc[2][1], x45, d1);
            FMA2(acc[2][2], x45, d2); FMA2(acc[2][3], x45, d3);
            FMA2(acc[3][0], x67, d0); FMA2(acc[3][1], x67, d1);
            FMA2(acc[3][2], x67, d2); FMA2(acc[3][3], x67, d3);

            xa += XS_STRIDE * 4;
            ea += ES_STRIDE * 4;
        }

        // ---- fold chunk scores into running per-token best ----
        const int cbase = v0 + (lane << 2);
        #pragma unroll
        for (int tp = 0; tp < 4; tp++) {
            #pragma unroll
            for (int j = 0; j < 4; j++) {
                const uint64_t a = acc[tp][j];
                const float lo = __uint_as_float((unsigned)(a & 0xffffffffu));
                const float hi = __uint_as_float((unsigned)(a >> 32));
                const float s0 = fmaf(-2.f, lo, en[j]);
                const float s1 = fmaf(-2.f, hi, en[j]);
                const int idx = cbase + j;
                if (s0 < best[2 * tp])     { best[2 * tp]     = s0; bidx[2 * tp]     = idx; }
                if (s1 < best[2 * tp + 1]) { best[2 * tp + 1] = s1; bidx[2 * tp + 1] = idx; }
            }
        }
    }

    // ---- warp-level argmin across lanes (lowest index wins ties) ----
    #pragma unroll
    for (int t = 0; t < 8; t++) {
        float s = best[t]; int b = bidx[t];
        #pragma unroll
        for (int off = 16; off; off >>= 1) {
            const float so = __shfl_xor_sync(0xffffffffu, s, off);
            const int   bo = __shfl_xor_sync(0xffffffffu, b, off);
            if (so < s || (so == s && bo < b)) { s = so; b = bo; }
        }
        if (lane == 0) g_codes[g * NTOK + n0 + w * 8 + t] = b;
    }
}

// ---------------------------------------------------------------------------
// Kernel 2: gather quantized output. quant[n][g*128+h] = embed[g][code][h].
// float4-granular; each warp handles one (n,g) row -> broadcast code load,
// coalesced 512B embed row (L2-resident).
// ---------------------------------------------------------------------------
__global__ void pq_gather_kernel(const float* __restrict__ embed,
                                 float4* __restrict__ outq) {
    const int i  = blockIdx.x * blockDim.x + threadIdx.x;  // over 4,194,304 float4s
    const int h4 = i & 31;
    const int gg = (i >> 5) & 7;
    const int n  = i >> 8;
    const int c  = g_codes[gg * NTOK + n];
    outq[i] = reinterpret_cast<const float4*>(embed)[((gg << 9) + c) * 32 + h4];
}

// Kernel 3: codes output as float, layout (n, g).
__global__ void pq_codes_kernel(float* __restrict__ outc) {
    const int i = blockIdx.x * blockDim.x + threadIdx.x;   // 131072
    outc[i] = (float)g_codes[(i & 7) * NTOK + (i >> 3)];
}

// ---------------------------------------------------------------------------
extern "C" void kernel_launch(void* const* d_in, const int* in_sizes, int n_in,
                              void* d_out, int out_size) {
    const float* x     = (const float*)d_in[0];
    const float* embed = (const float*)d_in[1];
    float* out = (float*)d_out;

    cudaFuncSetAttribute(pq_argmin_kernel,
                         cudaFuncAttributeMaxDynamicSharedMemorySize,
                         SMEM_FLOATS * 4);

    pq_enorm_kernel<<<512, 256>>>(embed);
    pq_argmin_kernel<<<dim3(NTOK / TILE_N, G), 256, SMEM_FLOATS * 4>>>(x, embed);
    pq_gather_kernel<<<(NTOK * G * HDIM / 4) / 256, 256>>>(embed, (float4*)out);
    pq_codes_kernel<<<(NTOK * G) / 256, 256>>>(out + (size_t)NTOK * G * HDIM);
}

// round 11
// speedup vs baseline: 2.1290x; 2.1290x over previous
#include <cuda_runtime.h>
#include <cuda_fp16.h>
#include <mma.h>
#include <cstdint>

using namespace nvcuda;

// ---------------------------------------------------------------------------
// Problem constants
// ---------------------------------------------------------------------------
#define G      8
#define VCODES 512
#define HDIM   128
#define NTOK   16384          // B*T
#define TILE_M 128            // tokens per CTA
#define TILE_C 64             // codes per chunk
#define NCHUNK 8

#define LDM_H   136           // halves per row (128 + 4-seg pad), 272 B
#define ROWB    272
#define XPLANE_B (128 * ROWB)         // 34816 B
#define EPLANE_B (TILE_C * ROWB)      // 17408 B
#define EBUF_B   (2 * EPLANE_B)       // hi+lo planes: 34816 B

#define SM_XH   0
#define SM_XL   XPLANE_B
#define SM_E    (2 * XPLANE_B)                 // 69632: two e buffers follow
#define SM_SC   (SM_E + 2 * EBUF_B)            // 139264: per-warp score scratch
#define SCRATCH_W (32 * 36 * 4)                // 4608 B per warp
#define SM_EN   (SM_SC + 8 * SCRATCH_W)        // 176128: 512 f32 e-norms
#define SM_TOTAL (SM_EN + 2048)                // 178176 B

#define ESTRIDE (G * VCODES * HDIM)

// ---------------------------------------------------------------------------
// Device scratch (no allocation allowed)
// ---------------------------------------------------------------------------
__device__ int    g_codes[G * NTOK];
__device__ float  g_enorm[G * VCODES];
__device__ __half g_esplit[2ull * ESTRIDE];   // [plane][g][v][k]

// ---------------------------------------------------------------------------
#define CP_ASYNC16(SADDR, GPTR) \
    asm volatile("cp.async.cg.shared.global [%0], [%1], 16;" \
        :: "r"(SADDR), "l"(GPTR) : "memory")
#define CP_COMMIT() asm volatile("cp.async.commit_group;" ::: "memory")
#define CP_WAIT1()  asm volatile("cp.async.wait_group 1;" ::: "memory")
#define CP_WAIT0()  asm volatile("cp.async.wait_group 0;" ::: "memory")

// ---------------------------------------------------------------------------
// Kernel: split embed into 2 fp16 planes [plane][g][v][k]
// ---------------------------------------------------------------------------
__global__ void pq_split_e_kernel(const float* __restrict__ embed) {
    const int i = blockIdx.x * 256 + threadIdx.x;      // 524,288 elems
    const float v = embed[i];
    const __half h = __float2half_rn(v);
    const __half l = __float2half_rn(v - __half2float(h));
    g_esplit[i] = h;
    g_esplit[i + ESTRIDE] = l;
}

// Kernel: ||e||^2 per (g, code), exact fp32
__global__ void pq_enorm_kernel(const float* __restrict__ embed) {
    const int row  = blockIdx.x * 8 + (threadIdx.x >> 5);
    const int lane = threadIdx.x & 31;
    const float* e = embed + (size_t)row * HDIM;
    const float v0 = e[lane], v1 = e[lane + 32], v2 = e[lane + 64], v3 = e[lane + 96];
    float s = v0 * v0 + v1 * v1 + v2 * v2 + v3 * v3;
    #pragma unroll
    for (int off = 16; off; off >>= 1) s += __shfl_xor_sync(0xffffffffu, s, off);
    if (lane == 0) g_enorm[row] = s;
}

// ---------------------------------------------------------------------------
// cp.async one e chunk: 2 planes x 64 code-rows x 16 segs of 16B = 2048 segs
// ---------------------------------------------------------------------------
__device__ __forceinline__ void issue_e(uint32_t su, int buf, int g, int cstart,
                                        int tid) {
    const uint32_t sb = su + SM_E + buf * EBUF_B;
    #pragma unroll
    for (int t = 0; t < 8; t++) {
        const int j = t * 256 + tid;                    // 0..2047
        const int p = j >> 10, r = (j >> 4) & 63, sgm = j & 15;
        const __half* gp = g_esplit + (size_t)p * ESTRIDE
                         + ((size_t)(g * VCODES + cstart + r)) * HDIM + sgm * 8;
        const uint32_t sa = sb + p * EPLANE_B + r * ROWB + sgm * 16;
        CP_ASYNC16(sa, gp);
    }
}

// ---------------------------------------------------------------------------
// Main kernel: fp16 2-split 3-pass WMMA distance GEMM + per-lane argmin.
// CTA = 128 tokens x 1 group; 8 warps: wm = token quadrant, wn = code half.
// Warp tile = 32 tokens x 32 codes (2x2 m16n16k16 acc fragments).
// FIX vs R10: warps (wm,0) and (wm,1) each cover only HALF the codebook for
// the same 32 tokens; their partial argmins are now MERGED via smem instead
// of racing on the final g_codes store.
// ---------------------------------------------------------------------------
__global__ __launch_bounds__(256, 1) void pq_main_kernel(
    const float* __restrict__ x)
{
    extern __shared__ char smem[];
    const uint32_t su = (uint32_t)__cvta_generic_to_shared(smem);
    const int tid  = threadIdx.x, lane = tid & 31, w = tid >> 5;
    const int wm   = w >> 1, wn = w & 1;
    const int g    = blockIdx.y, n0 = blockIdx.x * TILE_M;

    // e-norms -> smem
    *(float*)(smem + SM_EN + tid * 4)         = g_enorm[g * VCODES + tid];
    *(float*)(smem + SM_EN + (tid + 256) * 4) = g_enorm[g * VCODES + 256 + tid];

    // start e chunk 0
    issue_e(su, 0, g, 0, tid);
    CP_COMMIT();

    // x prologue: load fp32, split to hi/lo fp16 planes (128 rows x 32 segs)
    #pragma unroll
    for (int t = 0; t < 16; t++) {
        const int j = t * 256 + tid;
        const int r = j >> 5, sg = j & 31;
        const float4 v = *reinterpret_cast<const float4*>(
            x + (size_t)(n0 + r) * (G * HDIM) + g * HDIM + sg * 4);
        const __half hx = __float2half_rn(v.x), hy = __float2half_rn(v.y);
        const __half hz = __float2half_rn(v.z), hw = __float2half_rn(v.w);
        __half2* ph = reinterpret_cast<__half2*>(smem + SM_XH + r * ROWB + sg * 8);
        ph[0] = __halves2half2(hx, hy);
        ph[1] = __halves2half2(hz, hw);
        const __half lx = __float2half_rn(v.x - __half2float(hx));
        const __half ly = __float2half_rn(v.y - __half2float(hy));
        const __half lz = __float2half_rn(v.z - __half2float(hz));
        const __half lw = __float2half_rn(v.w - __half2float(hw));
        __half2* pl = reinterpret_cast<__half2*>(smem + SM_XL + r * ROWB + sg * 8);
        pl[0] = __halves2half2(lx, ly);
        pl[1] = __halves2half2(lz, lw);
    }

    float best = 3.4e38f;
    int   bidx = 0;

    const float* s_en = reinterpret_cast<const float*>(smem + SM_EN);
    float* sc = reinterpret_cast<float*>(smem + SM_SC + w * SCRATCH_W);

    for (int c = 0; c < NCHUNK; c++) {
        if (c + 1 < NCHUNK) {
            issue_e(su, (c + 1) & 1, g, (c + 1) * TILE_C, tid);
            CP_COMMIT();
            CP_WAIT1();
        } else {
            CP_WAIT0();
        }
        __syncthreads();   // chunk c resident; x/enorm ready (c==0)

        wmma::fragment<wmma::accumulator, 16, 16, 16, float> acc[2][2];
        #pragma unroll
        for (int i = 0; i < 2; i++)
            #pragma unroll
            for (int j = 0; j < 2; j++)
                wmma::fill_fragment(acc[i][j], 0.0f);

        #pragma unroll
        for (int pass = 0; pass < 3; pass++) {
            // pass 0: xh*eh, 1: xh*el, 2: xl*eh
            const __half* xp = reinterpret_cast<const __half*>(
                smem + (pass == 2 ? SM_XL : SM_XH));
            const __half* ep = reinterpret_cast<const __half*>(
                smem + SM_E + (c & 1) * EBUF_B + (pass == 1 ? EPLANE_B : 0));
            #pragma unroll
            for (int ks = 0; ks < 8; ks++) {
                wmma::fragment<wmma::matrix_a, 16, 16, 16, __half,
                               wmma::row_major> A[2];
                wmma::fragment<wmma::matrix_b, 16, 16, 16, __half,
                               wmma::col_major> Bf[2];
                wmma::load_matrix_sync(A[0],
                    xp + (wm * 32 + 0)  * LDM_H + ks * 16, LDM_H);
                wmma::load_matrix_sync(A[1],
                    xp + (wm * 32 + 16) * LDM_H + ks * 16, LDM_H);
                wmma::load_matrix_sync(Bf[0],
                    ep + (wn * 32 + 0)  * LDM_H + ks * 16, LDM_H);
                wmma::load_matrix_sync(Bf[1],
                    ep + (wn * 32 + 16) * LDM_H + ks * 16, LDM_H);
                #pragma unroll
                for (int i = 0; i < 2; i++)
                    #pragma unroll
                    for (int j = 0; j < 2; j++)
                        wmma::mma_sync(acc[i][j], A[i], Bf[j], acc[i][j]);
            }
        }

        // scores -> per-warp scratch (row = token-in-warp, ldm 36)
        #pragma unroll
        for (int i = 0; i < 2; i++)
            #pragma unroll
            for (int j = 0; j < 2; j++)
                wmma::store_matrix_sync(sc + i * 16 * 36 + j * 16, acc[i][j],
                                        36, wmma::mem_row_major);
        __syncwarp();

        // lane scans its own token row (rotated cols -> conflict-free LDS)
        const int cbase = c * TILE_C + wn * 32;
        #pragma unroll
        for (int cc = 0; cc < 32; cc++) {
            const int ccr = (cc + lane) & 31;
            const float s = fmaf(-2.f, sc[lane * 36 + ccr], s_en[cbase + ccr]);
            const int col = cbase + ccr;
            if (s < best || (s == best && col < bidx)) { best = s; bidx = col; }
        }
        __syncthreads();   // e buffer + scratch free for reuse
    }

    // ---- merge the two code-half argmins (wn=0 vs wn=1) per token ----
    // (R10 bug: both wn warps raced on the same g_codes slot, each holding an
    //  argmin over only half the codebook -> ~50% of tokens wrong.)
    float* mb = reinterpret_cast<float*>(smem + SM_SC);         // [4][32]
    int*   mi = reinterpret_cast<int*>(smem + SM_SC + 512);     // [4][32]
    if (wn == 1) { mb[wm * 32 + lane] = best; mi[wm * 32 + lane] = bidx; }
    __syncthreads();
    if (wn == 0) {
        const float ob = mb[wm * 32 + lane];
        const int   oi = mi[wm * 32 + lane];
        if (ob < best || (ob == best && oi < bidx)) { best = ob; bidx = oi; }
        g_codes[g * NTOK + n0 + wm * 32 + lane] = bidx;
    }
}

// ---------------------------------------------------------------------------
// Gather quantized output: quant[n][g*128+h] = embed[g][code][h]
// ---------------------------------------------------------------------------
__global__ void pq_gather_kernel(const float* __restrict__ embed,
                                 float4* __restrict__ outq) {
    const int i  = blockIdx.x * blockDim.x + threadIdx.x;  // 4,194,304 float4s
    const int h4 = i & 31;
    const int gg = (i >> 5) & 7;
    const int n  = i >> 8;
    const int c  = g_codes[gg * NTOK + n];
    outq[i] = reinterpret_cast<const float4*>(embed)[((gg << 9) + c) * 32 + h4];
}

// codes output as float, layout (n, g)
__global__ void pq_codes_kernel(float* __restrict__ outc) {
    const int i = blockIdx.x * blockDim.x + threadIdx.x;   // 131072
    outc[i] = (float)g_codes[(i & 7) * NTOK + (i >> 3)];
}

// ---------------------------------------------------------------------------
extern "C" void kernel_launch(void* const* d_in, const int* in_sizes, int n_in,
                              void* d_out, int out_size) {
    const float* x     = (const float*)d_in[0];
    const float* embed = (const float*)d_in[1];
    float* out = (float*)d_out;

    cudaFuncSetAttribute(pq_main_kernel,
                         cudaFuncAttributeMaxDynamicSharedMemorySize, SM_TOTAL);

    pq_split_e_kernel<<<(G * VCODES * HDIM) / 256, 256>>>(embed);
    pq_enorm_kernel<<<512, 256>>>(embed);
    pq_main_kernel<<<dim3(NTOK / TILE_M, G), 256, SM_TOTAL>>>(x);
    pq_gather_kernel<<<(NTOK * G * HDIM / 4) / 256, 256>>>(embed, (float4*)out);
    pq_codes_kernel<<<(NTOK * G) / 256, 256>>>(out + (size_t)NTOK * G * HDIM);
}

// round 12
// speedup vs baseline: 2.3435x; 1.1008x over previous
#include <cuda_runtime.h>
#include <cuda_fp16.h>
#include <mma.h>
#include <cstdint>

using namespace nvcuda;

// ---------------------------------------------------------------------------
// Problem constants
// ---------------------------------------------------------------------------
#define G      8
#define VCODES 512
#define HDIM   128
#define NTOK   16384          // B*T
#define TILE_M 256            // tokens per CTA (8 warps x 32 tokens)
#define TILE_C 64             // codes per chunk
#define NCHUNK 8

#define LDM_H   136           // halves per row (128 + 4-seg pad), 272 B
#define ROWB    272
#define XPLANE_B (TILE_M * ROWB)      // 69632 B
#define EPLANE_B (TILE_C * ROWB)      // 17408 B
#define EBUF_B   (2 * EPLANE_B)       // hi+lo planes: 34816 B

#define SM_XH   0
#define SM_XL   XPLANE_B
#define SM_E    (2 * XPLANE_B)                 // 139264
#define SM_SC   (SM_E + 2 * EBUF_B)            // 208896: per-warp 16x20 scratch
#define SCRATCH_W (16 * 20 * 4)                // 1280 B per warp
#define SM_EN   (SM_SC + 8 * SCRATCH_W)        // 219136: 512 f32 e-norms
#define SM_TOTAL (SM_EN + 2048)                // 221184 B

#define ESTRIDE (G * VCODES * HDIM)

// ---------------------------------------------------------------------------
// Device scratch (no allocation allowed)
// ---------------------------------------------------------------------------
__device__ int    g_codes[G * NTOK];
__device__ float  g_enorm[G * VCODES];
__device__ __half g_esplit[2ull * ESTRIDE];   // [plane][g][v][k]

// ---------------------------------------------------------------------------
#define CP_ASYNC16(SADDR, GPTR) \
    asm volatile("cp.async.cg.shared.global [%0], [%1], 16;" \
        :: "r"(SADDR), "l"(GPTR) : "memory")
#define CP_COMMIT() asm volatile("cp.async.commit_group;" ::: "memory")
#define CP_WAIT1()  asm volatile("cp.async.wait_group 1;" ::: "memory")
#define CP_WAIT0()  asm volatile("cp.async.wait_group 0;" ::: "memory")

// ---------------------------------------------------------------------------
// Kernel: split embed into 2 fp16 planes [plane][g][v][k]
// ---------------------------------------------------------------------------
__global__ void pq_split_e_kernel(const float* __restrict__ embed) {
    const int i = blockIdx.x * 256 + threadIdx.x;      // 524,288 elems
    const float v = embed[i];
    const __half h = __float2half_rn(v);
    const __half l = __float2half_rn(v - __half2float(h));
    g_esplit[i] = h;
    g_esplit[i + ESTRIDE] = l;
}

// Kernel: ||e||^2 per (g, code), exact fp32
__global__ void pq_enorm_kernel(const float* __restrict__ embed) {
    const int row  = blockIdx.x * 8 + (threadIdx.x >> 5);
    const int lane = threadIdx.x & 31;
    const float* e = embed + (size_t)row * HDIM;
    const float v0 = e[lane], v1 = e[lane + 32], v2 = e[lane + 64], v3 = e[lane + 96];
    float s = v0 * v0 + v1 * v1 + v2 * v2 + v3 * v3;
    #pragma unroll
    for (int off = 16; off; off >>= 1) s += __shfl_xor_sync(0xffffffffu, s, off);
    if (lane == 0) g_enorm[row] = s;
}

// ---------------------------------------------------------------------------
// cp.async one e chunk: 2 planes x 64 code-rows x 16 segs of 16B = 2048 segs
// ---------------------------------------------------------------------------
__device__ __forceinline__ void issue_e(uint32_t su, int buf, int g, int cstart,
                                        int tid) {
    const uint32_t sb = su + SM_E + buf * EBUF_B;
    #pragma unroll
    for (int t = 0; t < 8; t++) {
        const int j = t * 256 + tid;                    // 0..2047
        const int p = j >> 10, r = (j >> 4) & 63, sgm = j & 15;
        const __half* gp = g_esplit + (size_t)p * ESTRIDE
                         + ((size_t)(g * VCODES + cstart + r)) * HDIM + sgm * 8;
        const uint32_t sa = sb + p * EPLANE_B + r * ROWB + sgm * 16;
        CP_ASYNC16(sa, gp);
    }
}

// ---------------------------------------------------------------------------
// Main kernel: fp16 2-split fused 3-term WMMA distance GEMM + argmin.
// CTA = 256 tokens x 1 group; 8 warps; warp tile = 32 tokens x 64 codes.
// Per ks: load xh/xl A-frags once (4 LDSM), per code-subtile load eh/el
// (2 LDSM) and issue 3 MMA terms (hh, hl, lh) -> 0.25 LDSM per HMMA.16816.
// No code-split across warps -> no cross-warp argmin merge needed.
// ---------------------------------------------------------------------------
__global__ __launch_bounds__(256, 1) void pq_main_kernel(
    const float* __restrict__ x)
{
    extern __shared__ char smem[];
    const uint32_t su = (uint32_t)__cvta_generic_to_shared(smem);
    const int tid  = threadIdx.x, lane = tid & 31, w = tid >> 5;
    const int g    = blockIdx.y, n0 = blockIdx.x * TILE_M;

    // e-norms -> smem
    *(float*)(smem + SM_EN + tid * 4)         = g_enorm[g * VCODES + tid];
    *(float*)(smem + SM_EN + (tid + 256) * 4) = g_enorm[g * VCODES + 256 + tid];

    // start e chunk 0
    issue_e(su, 0, g, 0, tid);
    CP_COMMIT();

    // x prologue: 256 rows x 32 segs; split fp32 -> hi/lo fp16 planes
    #pragma unroll
    for (int t = 0; t < 32; t++) {
        const int j = t * 256 + tid;
        const int r = j >> 5, sg = j & 31;
        const float4 v = *reinterpret_cast<const float4*>(
            x + (size_t)(n0 + r) * (G * HDIM) + g * HDIM + sg * 4);
        const __half hx = __float2half_rn(v.x), hy = __float2half_rn(v.y);
        const __half hz = __float2half_rn(v.z), hw = __float2half_rn(v.w);
        __half2* ph = reinterpret_cast<__half2*>(smem + SM_XH + r * ROWB + sg * 8);
        ph[0] = __halves2half2(hx, hy);
        ph[1] = __halves2half2(hz, hw);
        const __half lx = __float2half_rn(v.x - __half2float(hx));
        const __half ly = __float2half_rn(v.y - __half2float(hy));
        const __half lz = __float2half_rn(v.z - __half2float(hz));
        const __half lw = __float2half_rn(v.w - __half2float(hw));
        __half2* pl = reinterpret_cast<__half2*>(smem + SM_XL + r * ROWB + sg * 8);
        pl[0] = __halves2half2(lx, ly);
        pl[1] = __halves2half2(lz, lw);
    }

    float best[2];
    int   bidx[2];
    #pragma unroll
    for (int i = 0; i < 2; i++) { best[i] = 3.4e38f; bidx[i] = 0; }

    const float* s_en = reinterpret_cast<const float*>(smem + SM_EN);
    float* sc = reinterpret_cast<float*>(smem + SM_SC + w * SCRATCH_W);
    const int row_in_frag = lane >> 1;
    const int cbase_lane  = (lane & 1) * 8;

    for (int c = 0; c < NCHUNK; c++) {
        if (c + 1 < NCHUNK) {
            issue_e(su, (c + 1) & 1, g, (c + 1) * TILE_C, tid);
            CP_COMMIT();
            CP_WAIT1();
        } else {
            CP_WAIT0();
        }
        __syncthreads();   // chunk c resident; x/enorm ready (c==0)

        wmma::fragment<wmma::accumulator, 16, 16, 16, float> acc[2][4];
        #pragma unroll
        for (int i = 0; i < 2; i++)
            #pragma unroll
            for (int j = 0; j < 4; j++)
                wmma::fill_fragment(acc[i][j], 0.0f);

        const __half* xh = reinterpret_cast<const __half*>(smem + SM_XH);
        const __half* xl = reinterpret_cast<const __half*>(smem + SM_XL);
        const __half* eh = reinterpret_cast<const __half*>(
            smem + SM_E + (c & 1) * EBUF_B);
        const __half* el = eh + EPLANE_B / 2;   // halves, not bytes

        #pragma unroll
        for (int ks = 0; ks < 8; ks++) {
            wmma::fragment<wmma::matrix_a, 16, 16, 16, __half,
                           wmma::row_major> Ah[2], Al[2];
            wmma::load_matrix_sync(Ah[0], xh + (w * 32 + 0)  * LDM_H + ks * 16, LDM_H);
            wmma::load_matrix_sync(Ah[1], xh + (w * 32 + 16) * LDM_H + ks * 16, LDM_H);
            wmma::load_matrix_sync(Al[0], xl + (w * 32 + 0)  * LDM_H + ks * 16, LDM_H);
            wmma::load_matrix_sync(Al[1], xl + (w * 32 + 16) * LDM_H + ks * 16, LDM_H);
            #pragma unroll
            for (int j = 0; j < 4; j++) {
                wmma::fragment<wmma::matrix_b, 16, 16, 16, __half,
                               wmma::col_major> Bh, Bl;
                wmma::load_matrix_sync(Bh, eh + j * 16 * LDM_H + ks * 16, LDM_H);
                wmma::load_matrix_sync(Bl, el + j * 16 * LDM_H + ks * 16, LDM_H);
                #pragma unroll
                for (int i = 0; i < 2; i++) {
                    wmma::mma_sync(acc[i][j], Ah[i], Bh, acc[i][j]);  // hh
                    wmma::mma_sync(acc[i][j], Ah[i], Bl, acc[i][j]);  // hl
                    wmma::mma_sync(acc[i][j], Al[i], Bh, acc[i][j]);  // lh
                }
            }
        }

        // epilogue: per-fragment smem round-trip, fold into per-token argmin
        #pragma unroll
        for (int i = 0; i < 2; i++) {
            #pragma unroll
            for (int j = 0; j < 4; j++) {
                wmma::store_matrix_sync(sc, acc[i][j], 20, wmma::mem_row_major);
                __syncwarp();
                const int colb = c * TILE_C + j * 16 + cbase_lane;
                #pragma unroll
                for (int t = 0; t < 8; t++) {
                    const float s = fmaf(-2.f, sc[row_in_frag * 20 + cbase_lane + t],
                                         s_en[colb + t]);
                    const int col = colb + t;
                    if (s < best[i] || (s == best[i] && col < bidx[i])) {
                        best[i] = s; bidx[i] = col;
                    }
                }
                __syncwarp();   // scratch reused by next fragment
            }
        }
        __syncthreads();   // e buffer free for refill
    }

    // merge the two lanes sharing each token row (lane ^ 1)
    #pragma unroll
    for (int i = 0; i < 2; i++) {
        const float so = __shfl_xor_sync(0xffffffffu, best[i], 1);
        const int   bo = __shfl_xor_sync(0xffffffffu, bidx[i], 1);
        if (so < best[i] || (so == best[i] && bo < bidx[i])) {
            best[i] = so; bidx[i] = bo;
        }
        if (!(lane & 1))
            g_codes[g * NTOK + n0 + w * 32 + i * 16 + row_in_frag] = bidx[i];
    }
}

// ---------------------------------------------------------------------------
// Gather quantized output + codes output (fused).
// quant[n][g*128+h] = embed[g][code][h];  codes[n][g] = code (as float)
// ---------------------------------------------------------------------------
__global__ void pq_gather_kernel(const float* __restrict__ embed,
                                 float4* __restrict__ outq,
                                 float* __restrict__ outc) {
    const int i  = blockIdx.x * blockDim.x + threadIdx.x;  // 4,194,304 float4s
    const int h4 = i & 31;
    const int gg = (i >> 5) & 7;
    const int n  = i >> 8;
    const int c  = g_codes[gg * NTOK + n];
    outq[i] = reinterpret_cast<const float4*>(embed)[((gg << 9) + c) * 32 + h4];
    if (h4 == 0) outc[n * 8 + gg] = (float)c;
}

// ---------------------------------------------------------------------------
extern "C" void kernel_launch(void* const* d_in, const int* in_sizes, int n_in,
                              void* d_out, int out_size) {
    const float* x     = (const float*)d_in[0];
    const float* embed = (const float*)d_in[1];
    float* out = (float*)d_out;

    cudaFuncSetAttribute(pq_main_kernel,
                         cudaFuncAttributeMaxDynamicSharedMemorySize, SM_TOTAL);

    pq_split_e_kernel<<<(G * VCODES * HDIM) / 256, 256>>>(embed);
    pq_enorm_kernel<<<512, 256>>>(embed);
    pq_main_kernel<<<dim3(NTOK / TILE_M, G), 256, SM_TOTAL>>>(x);
    pq_gather_kernel<<<(NTOK * G * HDIM / 4) / 256, 256>>>(
        embed, (float4*)out, out + (size_t)NTOK * G * HDIM);
}